// round 6
// baseline (speedup 1.0000x reference)
#include <cuda_runtime.h>
#include <cuda_bf16.h>

// RangeLoss: mean((preds - adjusted_target)^2), N=8M rows, F=4 -> one float4/row.
// Single-kernel HBM-streaming reduction. Deterministic via int64 fixed-point atomics.
// R6: R3 config (best profiled: unroll-2, 2368 blocks) + cs/L2::256B load hint.

__device__ unsigned long long g_acc   = 0ULL;
__device__ unsigned int       g_count = 0u;

#define FXP_SCALE 268435456.0  // 2^28

__device__ __forceinline__ float4 ldg_cs256(const float4* p) {
    float4 v;
    asm volatile("ld.global.cs.L2::256B.v4.f32 {%0,%1,%2,%3}, [%4];"
                 : "=f"(v.x), "=f"(v.y), "=f"(v.z), "=f"(v.w)
                 : "l"(p));
    return v;
}

__device__ __forceinline__ float row_loss(float4 p, float4 t) {
    // Step A, column 0
    if (fabsf(p.x) < 0.01f && t.x == 0.0f) t.x = p.x;
    if (p.x > 0.99f && p.x < 1.01f && t.x == 1.0f) t.x = p.x;
    // Step A, column 1
    if (fabsf(p.y) < 0.01f && t.y == 0.0f) t.y = p.y;
    if (p.y > 0.99f && p.y < 1.01f && t.y == 1.0f) t.y = p.y;
    // Step B, column 1 (uses post-step-A t.y)
    bool cond = (p.z > 0.9f) || ((p.y * 1.05f > t.y) && (p.y * 0.95f < t.y));
    if (cond) t.y = p.y;

    float d0 = p.x - t.x;
    float d1 = p.y - t.y;
    float d2 = p.z - t.z;
    float d3 = p.w - t.w;
    return d0 * d0 + d1 * d1 + d2 * d2 + d3 * d3;
}

__global__ void __launch_bounds__(256, 8)
rangeloss_kernel(const float4* __restrict__ preds,
                 const float4* __restrict__ target,
                 int n_rows,
                 float* __restrict__ out,
                 unsigned int n_blocks,
                 double inv_count) {
    const int stride  = gridDim.x * blockDim.x;
    const int stride2 = stride * 2;
    int idx = blockIdx.x * blockDim.x + threadIdx.x;

    float facc = 0.0f;

    // Unroll-by-2: 4 outstanding LDG.128, 16 data regs (R3 config, best profiled).
    for (; idx + stride < n_rows; idx += stride2) {
        float4 p0 = ldg_cs256(&preds[idx]);
        float4 t0 = ldg_cs256(&target[idx]);
        float4 p1 = ldg_cs256(&preds[idx + stride]);
        float4 t1 = ldg_cs256(&target[idx + stride]);
        facc += row_loss(p0, t0);
        facc += row_loss(p1, t1);
    }
    if (idx < n_rows) {
        float4 p = ldg_cs256(&preds[idx]);
        float4 t = ldg_cs256(&target[idx]);
        facc += row_loss(p, t);
    }

    // Warp reduce in float (per-lane sums are small; fp32 ample for 1e-3 tol)
    #pragma unroll
    for (int off = 16; off > 0; off >>= 1)
        facc += __shfl_down_sync(0xFFFFFFFFu, facc, off);

    __shared__ float swarp[8];  // 256 threads = 8 warps
    int lane = threadIdx.x & 31;
    int wid  = threadIdx.x >> 5;
    if (lane == 0) swarp[wid] = facc;
    __syncthreads();

    if (threadIdx.x == 0) {
        double bsum = 0.0;
        #pragma unroll
        for (int w = 0; w < 8; w++) bsum += (double)swarp[w];

        // Deterministic device-wide accumulation: fixed-point int64
        unsigned long long fx = (unsigned long long)(bsum * FXP_SCALE + 0.5);
        atomicAdd(&g_acc, fx);
        __threadfence();
        unsigned int done = atomicAdd(&g_count, 1u);
        if (done == n_blocks - 1u) {
            unsigned long long total_fx = atomicAdd(&g_acc, 0ULL);
            double total = (double)total_fx / FXP_SCALE;
            out[0] = (float)(total * inv_count);
            // Reset for next graph replay
            atomicExch(&g_acc, 0ULL);
            atomicExch(&g_count, 0u);
        }
    }
}

extern "C" void kernel_launch(void* const* d_in, const int* in_sizes, int n_in,
                              void* d_out, int out_size) {
    const float4* preds  = (const float4*)d_in[0];
    const float4* target = (const float4*)d_in[1];
    float* out = (float*)d_out;

    long long n_elems = (long long)in_sizes[0];   // N * 4
    int n_rows = (int)(n_elems / 4);

    const int threads = 256;
    int blocks = 148 * 16;  // 2368 blocks: R3's best-profiled configuration
    if ((long long)blocks * threads > (long long)n_rows)
        blocks = (n_rows + threads - 1) / threads;
    if (blocks < 1) blocks = 1;

    rangeloss_kernel<<<blocks, threads>>>(preds, target, n_rows, out,
                                          (unsigned int)blocks,
                                          1.0 / (double)n_elems);
}

// round 7
// speedup vs baseline: 1.0133x; 1.0133x over previous
#include <cuda_runtime.h>
#include <cuda_bf16.h>

// RangeLoss: mean((preds - adjusted_target)^2), N=8M rows, F=4 -> one float4/row.
// Single-kernel HBM-streaming reduction. Deterministic via int64 fixed-point atomics.
// R7: unroll-1 (MLP_p1=2) to stay under the ~248-entry L1tex wavefront queue
//     (64 warps x 2 LDG.128 = 128 entries) and kill cross-CTA queue-contention spread.

__device__ unsigned long long g_acc   = 0ULL;
__device__ unsigned int       g_count = 0u;

#define FXP_SCALE 268435456.0  // 2^28

__device__ __forceinline__ float row_loss(float4 p, float4 t) {
    // Step A, column 0
    if (fabsf(p.x) < 0.01f && t.x == 0.0f) t.x = p.x;
    if (p.x > 0.99f && p.x < 1.01f && t.x == 1.0f) t.x = p.x;
    // Step A, column 1
    if (fabsf(p.y) < 0.01f && t.y == 0.0f) t.y = p.y;
    if (p.y > 0.99f && p.y < 1.01f && t.y == 1.0f) t.y = p.y;
    // Step B, column 1 (uses post-step-A t.y)
    bool cond = (p.z > 0.9f) || ((p.y * 1.05f > t.y) && (p.y * 0.95f < t.y));
    if (cond) t.y = p.y;

    float d0 = p.x - t.x;
    float d1 = p.y - t.y;
    float d2 = p.z - t.z;
    float d3 = p.w - t.w;
    return d0 * d0 + d1 * d1 + d2 * d2 + d3 * d3;
}

__global__ void __launch_bounds__(256, 8)
rangeloss_kernel(const float4* __restrict__ preds,
                 const float4* __restrict__ target,
                 int n_rows,
                 float* __restrict__ out,
                 unsigned int n_blocks,
                 double inv_count) {
    const int stride = gridDim.x * blockDim.x;
    int idx = blockIdx.x * blockDim.x + threadIdx.x;

    float facc = 0.0f;

    // Unroll-1: exactly 2 in-flight LDG.128 per warp-iteration.
    // SM-wide queue load = 64 warps * 2 = 128 < 248 L1tex wavefront entries.
    for (; idx < n_rows; idx += stride) {
        float4 p = __ldcs(&preds[idx]);
        float4 t = __ldcs(&target[idx]);
        facc += row_loss(p, t);
    }

    // Warp reduce in float (per-lane sums are small; fp32 ample for 1e-3 tol)
    #pragma unroll
    for (int off = 16; off > 0; off >>= 1)
        facc += __shfl_down_sync(0xFFFFFFFFu, facc, off);

    __shared__ float swarp[8];  // 256 threads = 8 warps
    int lane = threadIdx.x & 31;
    int wid  = threadIdx.x >> 5;
    if (lane == 0) swarp[wid] = facc;
    __syncthreads();

    if (threadIdx.x == 0) {
        double bsum = 0.0;
        #pragma unroll
        for (int w = 0; w < 8; w++) bsum += (double)swarp[w];

        // Deterministic device-wide accumulation: fixed-point int64
        unsigned long long fx = (unsigned long long)(bsum * FXP_SCALE + 0.5);
        atomicAdd(&g_acc, fx);
        __threadfence();
        unsigned int done = atomicAdd(&g_count, 1u);
        if (done == n_blocks - 1u) {
            unsigned long long total_fx = atomicAdd(&g_acc, 0ULL);
            double total = (double)total_fx / FXP_SCALE;
            out[0] = (float)(total * inv_count);
            // Reset for next graph replay
            atomicExch(&g_acc, 0ULL);
            atomicExch(&g_count, 0u);
        }
    }
}

extern "C" void kernel_launch(void* const* d_in, const int* in_sizes, int n_in,
                              void* d_out, int out_size) {
    const float4* preds  = (const float4*)d_in[0];
    const float4* target = (const float4*)d_in[1];
    float* out = (float*)d_out;

    long long n_elems = (long long)in_sizes[0];   // N * 4
    int n_rows = (int)(n_elems / 4);

    const int threads = 256;
    int blocks = 148 * 8;  // exactly one resident wave at occ=8
    if ((long long)blocks * threads > (long long)n_rows)
        blocks = (n_rows + threads - 1) / threads;
    if (blocks < 1) blocks = 1;

    rangeloss_kernel<<<blocks, threads>>>(preds, target, n_rows, out,
                                          (unsigned int)blocks,
                                          1.0 / (double)n_elems);
}

// round 8
// speedup vs baseline: 1.0141x; 1.0007x over previous
#include <cuda_runtime.h>
#include <cuda_bf16.h>

// RangeLoss: mean((preds - adjusted_target)^2), N=8M rows, F=4 -> one float4/row.
// Single-kernel HBM-streaming reduction. Deterministic via int64 fixed-point atomics.
// R8: R7 (unroll-1, occ-8 single wave — best measured, 99% of LTS cap) with
//     byte-stepped pointer arithmetic to trim the per-iteration IMAD chain.

__device__ unsigned long long g_acc   = 0ULL;
__device__ unsigned int       g_count = 0u;

#define FXP_SCALE 268435456.0  // 2^28

__device__ __forceinline__ float row_loss(float4 p, float4 t) {
    // Step A, column 0
    if (fabsf(p.x) < 0.01f && t.x == 0.0f) t.x = p.x;
    if (p.x > 0.99f && p.x < 1.01f && t.x == 1.0f) t.x = p.x;
    // Step A, column 1
    if (fabsf(p.y) < 0.01f && t.y == 0.0f) t.y = p.y;
    if (p.y > 0.99f && p.y < 1.01f && t.y == 1.0f) t.y = p.y;
    // Step B, column 1 (uses post-step-A t.y)
    bool cond = (p.z > 0.9f) || ((p.y * 1.05f > t.y) && (p.y * 0.95f < t.y));
    if (cond) t.y = p.y;

    float d0 = p.x - t.x;
    float d1 = p.y - t.y;
    float d2 = p.z - t.z;
    float d3 = p.w - t.w;
    return d0 * d0 + d1 * d1 + d2 * d2 + d3 * d3;
}

__global__ void __launch_bounds__(256, 8)
rangeloss_kernel(const float4* __restrict__ preds,
                 const float4* __restrict__ target,
                 int n_rows,
                 float* __restrict__ out,
                 unsigned int n_blocks,
                 double inv_count) {
    const int gid    = blockIdx.x * blockDim.x + threadIdx.x;
    const int stride = gridDim.x * blockDim.x;

    // Byte-stepped pointers: one 64-bit add per array per iteration (no IMAD chain).
    const float4* pp = preds  + gid;
    const float4* tp = target + gid;
    const float4* pend = preds + n_rows;

    float facc = 0.0f;

    // Unroll-1: exactly 2 in-flight LDG.128 per warp-iteration.
    // SM-wide queue load = 64 warps * 2 = 128 < ~248 L1tex wavefront entries.
    for (; pp < pend; pp += stride, tp += stride) {
        float4 p = __ldcs(pp);
        float4 t = __ldcs(tp);
        facc += row_loss(p, t);
    }

    // Warp reduce in float (per-lane sums are small; fp32 ample for 1e-3 tol)
    #pragma unroll
    for (int off = 16; off > 0; off >>= 1)
        facc += __shfl_down_sync(0xFFFFFFFFu, facc, off);

    __shared__ float swarp[8];  // 256 threads = 8 warps
    int lane = threadIdx.x & 31;
    int wid  = threadIdx.x >> 5;
    if (lane == 0) swarp[wid] = facc;
    __syncthreads();

    if (threadIdx.x == 0) {
        double bsum = 0.0;
        #pragma unroll
        for (int w = 0; w < 8; w++) bsum += (double)swarp[w];

        // Deterministic device-wide accumulation: fixed-point int64
        unsigned long long fx = (unsigned long long)(bsum * FXP_SCALE + 0.5);
        atomicAdd(&g_acc, fx);
        __threadfence();
        unsigned int done = atomicAdd(&g_count, 1u);
        if (done == n_blocks - 1u) {
            unsigned long long total_fx = atomicAdd(&g_acc, 0ULL);
            double total = (double)total_fx / FXP_SCALE;
            out[0] = (float)(total * inv_count);
            // Reset for next graph replay
            atomicExch(&g_acc, 0ULL);
            atomicExch(&g_count, 0u);
        }
    }
}

extern "C" void kernel_launch(void* const* d_in, const int* in_sizes, int n_in,
                              void* d_out, int out_size) {
    const float4* preds  = (const float4*)d_in[0];
    const float4* target = (const float4*)d_in[1];
    float* out = (float*)d_out;

    long long n_elems = (long long)in_sizes[0];   // N * 4
    int n_rows = (int)(n_elems / 4);

    const int threads = 256;
    int blocks = 148 * 8;  // exactly one resident wave at occ=8
    if ((long long)blocks * threads > (long long)n_rows)
        blocks = (n_rows + threads - 1) / threads;
    if (blocks < 1) blocks = 1;

    rangeloss_kernel<<<blocks, threads>>>(preds, target, n_rows, out,
                                          (unsigned int)blocks,
                                          1.0 / (double)n_elems);
}